// round 6
// baseline (speedup 1.0000x reference)
#include <cuda_runtime.h>
#include <cuda_bf16.h>

#define BATCH 2
#define NPTS  65536
#define KNN   16
#define DCH   32

// One thread handles (b, n, quad-of-4 k's). All 64 output channels for that
// (n, k-quad) are written as float4 write-through stores: output is
// write-once, never re-read -> bypass L2 dirty-line management entirely.
__global__ __launch_bounds__(256) void lse_kernel(
    const float* __restrict__ coords,    // (B, N, 3)
    const float* __restrict__ features,  // (B, D, N, 1)
    const int*   __restrict__ idx,       // (B, N, K)
    const float* __restrict__ w,         // (D, 10)
    const float* __restrict__ bias,      // (D,)
    const float* __restrict__ gamma,
    const float* __restrict__ beta,
    const float* __restrict__ mean,
    const float* __restrict__ var,
    float* __restrict__ out)             // (B, 2D, N, K)
{
    // Folded per-channel params:
    // dot(w, [ext, nb, ext-nb, dist]) = (w0:3 + w6:9)·ext + (w3:6 - w6:9)·nb + w9*dist
    __shared__ float4 s_wa[DCH];  // we.x, we.y, we.z, wn.x
    __shared__ float4 s_wb[DCH];  // wn.y, wn.z, wd,   bias'
    int t = threadIdx.x;
    if (t < DCH) {
        float sc = gamma[t] * rsqrtf(var[t] + 1e-5f);
        const float* wr = w + t * 10;
        float w0 = wr[0], w1 = wr[1], w2 = wr[2], w3 = wr[3], w4 = wr[4];
        float w5 = wr[5], w6 = wr[6], w7 = wr[7], w8 = wr[8], w9 = wr[9];
        s_wa[t] = make_float4((w0 + w6) * sc, (w1 + w7) * sc, (w2 + w8) * sc,
                              (w3 - w6) * sc);
        s_wb[t] = make_float4((w4 - w7) * sc, (w5 - w8) * sc, w9 * sc,
                              (bias[t] - mean[t]) * sc + beta[t]);
    }
    __syncthreads();

    int gid = blockIdx.x * blockDim.x + t;       // 0 .. B*N*4 - 1
    int kq  = gid & 3;                           // which quad of k
    int n   = (gid >> 2) & (NPTS - 1);
    int b   = gid >> 18;                         // gid / (4*N)

    const float* cb = coords + (size_t)b * NPTS * 3;
    float cx = cb[(size_t)n * 3 + 0];
    float cy = cb[(size_t)n * 3 + 1];
    float cz = cb[(size_t)n * 3 + 2];

    int4 ii = *reinterpret_cast<const int4*>(
        idx + ((size_t)b * NPTS + (size_t)n) * KNN + kq * 4);

    float nx[4], ny[4], nz[4], dist[4];
#pragma unroll
    for (int j = 0; j < 4; j++) {
        int id = (&ii.x)[j];
        float x = __ldg(cb + (size_t)id * 3 + 0);
        float y = __ldg(cb + (size_t)id * 3 + 1);
        float z = __ldg(cb + (size_t)id * 3 + 2);
        nx[j] = x; ny[j] = y; nz[j] = z;
        float ddx = cx - x, ddy = cy - y, ddz = cz - z;
        dist[j] = sqrtf(ddx * ddx + ddy * ddy + ddz * ddz);
    }

    const size_t cstride = (size_t)NPTS * KNN;   // per-channel stride in out
    size_t out_base = (size_t)b * 2 * DCH * cstride + (size_t)n * KNN
                      + (size_t)kq * 4;

    // Computed half: y = relu(conv+BN)
#pragma unroll
    for (int o = 0; o < DCH; o++) {
        float4 wa = s_wa[o];
        float4 wb = s_wb[o];
        float base = wb.w + wa.x * cx + wa.y * cy + wa.z * cz;
        float4 r;
        float* rp = &r.x;
#pragma unroll
        for (int j = 0; j < 4; j++) {
            float v = base + wa.w * nx[j] + wb.x * ny[j] + wb.y * nz[j]
                           + wb.z * dist[j];
            rp[j] = fmaxf(v, 0.0f);
        }
        __stwt(reinterpret_cast<float4*>(out + out_base + (size_t)o * cstride),
               r);
    }

    // Broadcast half: features replicated across K
    const float* fb = features + (size_t)b * DCH * NPTS + (size_t)n;
    size_t fout = out_base + (size_t)DCH * cstride;
#pragma unroll
    for (int c = 0; c < DCH; c++) {
        float f = __ldg(fb + (size_t)c * NPTS);
        __stwt(reinterpret_cast<float4*>(out + fout + (size_t)c * cstride),
               make_float4(f, f, f, f));
    }
}

extern "C" void kernel_launch(void* const* d_in, const int* in_sizes, int n_in,
                              void* d_out, int out_size) {
    const float* coords   = (const float*)d_in[0];
    const float* features = (const float*)d_in[1];
    const int*   idx      = (const int*)d_in[2];
    const float* w        = (const float*)d_in[3];
    const float* bias     = (const float*)d_in[4];
    const float* gamma    = (const float*)d_in[5];
    const float* beta     = (const float*)d_in[6];
    const float* mean     = (const float*)d_in[7];
    const float* var      = (const float*)d_in[8];
    float* out = (float*)d_out;

    const int total   = BATCH * NPTS * 4;   // one thread per (b, n, k-quad)
    const int threads = 256;
    const int blocks  = total / threads;    // 2048
    lse_kernel<<<blocks, threads>>>(coords, features, idx, w, bias,
                                    gamma, beta, mean, var, out);
}

// round 7
// speedup vs baseline: 1.0055x; 1.0055x over previous
#include <cuda_runtime.h>
#include <cuda_bf16.h>

#define BATCH 2
#define NPTS  65536
#define KNN   16
#define DCH   32

// 256-bit streaming store (Blackwell sm_100a): 8 floats, 32B-aligned.
__device__ __forceinline__ void stcs_v8(float* p,
                                        float a0, float a1, float a2, float a3,
                                        float a4, float a5, float a6, float a7) {
    asm volatile(
        "st.global.cs.v8.f32 [%0], {%1, %2, %3, %4, %5, %6, %7, %8};"
        :: "l"(p), "f"(a0), "f"(a1), "f"(a2), "f"(a3),
           "f"(a4), "f"(a5), "f"(a6), "f"(a7)
        : "memory");
}

// One thread handles (b, n, k-octet of 8). All 64 output channels for that
// (n, k-octet) written as one 32B st.global.cs.v8 each -> halves the store
// wavefront stream vs float4.
__global__ __launch_bounds__(256) void lse_kernel(
    const float* __restrict__ coords,    // (B, N, 3)
    const float* __restrict__ features,  // (B, D, N, 1)
    const int*   __restrict__ idx,       // (B, N, K)
    const float* __restrict__ w,         // (D, 10)
    const float* __restrict__ bias,      // (D,)
    const float* __restrict__ gamma,
    const float* __restrict__ beta,
    const float* __restrict__ mean,
    const float* __restrict__ var,
    float* __restrict__ out)             // (B, 2D, N, K)
{
    // Folded per-channel params:
    // dot(w, [ext, nb, ext-nb, dist]) = (w0:3 + w6:9)·ext + (w3:6 - w6:9)·nb + w9*dist
    __shared__ float4 s_wa[DCH];  // we.x, we.y, we.z, wn.x
    __shared__ float4 s_wb[DCH];  // wn.y, wn.z, wd,   bias'
    int t = threadIdx.x;
    if (t < DCH) {
        float sc = gamma[t] * rsqrtf(var[t] + 1e-5f);
        const float* wr = w + t * 10;
        float w0 = wr[0], w1 = wr[1], w2 = wr[2], w3 = wr[3], w4 = wr[4];
        float w5 = wr[5], w6 = wr[6], w7 = wr[7], w8 = wr[8], w9 = wr[9];
        s_wa[t] = make_float4((w0 + w6) * sc, (w1 + w7) * sc, (w2 + w8) * sc,
                              (w3 - w6) * sc);
        s_wb[t] = make_float4((w4 - w7) * sc, (w5 - w8) * sc, w9 * sc,
                              (bias[t] - mean[t]) * sc + beta[t]);
    }
    __syncthreads();

    int gid = blockIdx.x * blockDim.x + t;       // 0 .. B*N*2 - 1
    int kh  = gid & 1;                           // which octet of k
    int n   = (gid >> 1) & (NPTS - 1);
    int b   = gid >> 17;                         // gid / (2*N)

    const float* cb = coords + (size_t)b * NPTS * 3;
    float cx = cb[(size_t)n * 3 + 0];
    float cy = cb[(size_t)n * 3 + 1];
    float cz = cb[(size_t)n * 3 + 2];

    const int* ip = idx + ((size_t)b * NPTS + (size_t)n) * KNN + kh * 8;
    int4 i0 = *reinterpret_cast<const int4*>(ip);
    int4 i1 = *reinterpret_cast<const int4*>(ip + 4);
    int ids[8] = {i0.x, i0.y, i0.z, i0.w, i1.x, i1.y, i1.z, i1.w};

    float nx[8], ny[8], nz[8], dist[8];
#pragma unroll
    for (int j = 0; j < 8; j++) {
        int id = ids[j];
        float x = __ldg(cb + (size_t)id * 3 + 0);
        float y = __ldg(cb + (size_t)id * 3 + 1);
        float z = __ldg(cb + (size_t)id * 3 + 2);
        nx[j] = x; ny[j] = y; nz[j] = z;
        float ddx = cx - x, ddy = cy - y, ddz = cz - z;
        dist[j] = sqrtf(ddx * ddx + ddy * ddy + ddz * ddz);
    }

    const size_t cstride = (size_t)NPTS * KNN;   // per-channel stride in out
    size_t out_base = (size_t)b * 2 * DCH * cstride + (size_t)n * KNN
                      + (size_t)kh * 8;

    // Computed half: y = relu(conv+BN)
#pragma unroll
    for (int o = 0; o < DCH; o++) {
        float4 wa = s_wa[o];
        float4 wb = s_wb[o];
        float base = wb.w + wa.x * cx + wa.y * cy + wa.z * cz;
        float r[8];
#pragma unroll
        for (int j = 0; j < 8; j++) {
            float v = base + wa.w * nx[j] + wb.x * ny[j] + wb.y * nz[j]
                           + wb.z * dist[j];
            r[j] = fmaxf(v, 0.0f);
        }
        stcs_v8(out + out_base + (size_t)o * cstride,
                r[0], r[1], r[2], r[3], r[4], r[5], r[6], r[7]);
    }

    // Broadcast half: features replicated across K
    const float* fb = features + (size_t)b * DCH * NPTS + (size_t)n;
    size_t fout = out_base + (size_t)DCH * cstride;
#pragma unroll
    for (int c = 0; c < DCH; c++) {
        float f = __ldg(fb + (size_t)c * NPTS);
        stcs_v8(out + fout + (size_t)c * cstride, f, f, f, f, f, f, f, f);
    }
}

extern "C" void kernel_launch(void* const* d_in, const int* in_sizes, int n_in,
                              void* d_out, int out_size) {
    const float* coords   = (const float*)d_in[0];
    const float* features = (const float*)d_in[1];
    const int*   idx      = (const int*)d_in[2];
    const float* w        = (const float*)d_in[3];
    const float* bias     = (const float*)d_in[4];
    const float* gamma    = (const float*)d_in[5];
    const float* beta     = (const float*)d_in[6];
    const float* mean     = (const float*)d_in[7];
    const float* var      = (const float*)d_in[8];
    float* out = (float*)d_out;

    const int total   = BATCH * NPTS * 2;   // one thread per (b, n, k-octet)
    const int threads = 256;
    const int blocks  = total / threads;    // 512
    lse_kernel<<<blocks, threads>>>(coords, features, idx, w, bias,
                                    gamma, beta, mean, var, out);
}